// round 14
// baseline (speedup 1.0000x reference)
#include <cuda_runtime.h>
#include <cstdint>

// CRF Viterbi decode: B=128, T=1024, K=128
// out[b,t,k] = one_hot(tags[b,t]) fp32
//
// 1 CTA/batch. Warp 0 runs the serial Viterbi recurrence. Candidate pruning
// masks are STATE-INDEPENDENT: for step t, i is a candidate only if
//   cl_{t-1}[i] + rmx[i] + Delta >= max_k(cl_{t-1}[k] + rmn[k]),
// where Delta = (tmax - tmin) + slack (M_{t-2} cancels from the interval
// bound bv in [M+tmin, M+tmax]). Producer warps 1-3 compute these masks
// (REDUX + ballots + decode) per logit row while staging the row into a
// double-buffered data ring; meta goes into a depth-3 ring. Warp 0's serial
// chain contains NO collectives except one SHFL pair for state broadcast.

static constexpr int B_ = 128;
static constexpr int T_ = 1024;
static constexpr int K_ = 128;
static constexpr int CHUNK = 16;                      // rows per ring buffer

// Shared memory layout (in 4-byte words)
static constexpr int TT_WORDS  = K_ * K_;             // 16384 row-major transitions
static constexpr int RMIN_OFF  = TT_WORDS;            // 16384
static constexpr int RMAX_OFF  = RMIN_OFF + K_;       // 16512
static constexpr int TAGS_OFF  = RMAX_OFF + K_;       // 16640
static constexpr int BP_OFF    = TAGS_OFF + T_;       // 17664 (u32/(t,lane): 4 packed u8 bp)
static constexpr int RING_OFF  = BP_OFF + T_ * 32;    // 50432 (2 x CHUNK x 128 floats)
static constexpr int META_OFF  = RING_OFF + 2 * CHUNK * K_;   // 54528 (3 x CHUNK x 8 u32)
static constexpr int DELTA_OFF = META_OFF + 3 * CHUNK * 8;    // 54912
static constexpr int SMEM_WORDS = DELTA_OFF + 8;      // 54920
static constexpr size_t SMEM_BYTES = (size_t)SMEM_WORDS * 4;  // 219680 B

// Monotone fp32 <-> ordered signed-int key
__device__ __forceinline__ int f2key(float x) {
    int i = __float_as_int(x);
    return i ^ ((i >> 31) & 0x7fffffff);
}
__device__ __forceinline__ float key2f(int k) {
    return __int_as_float(k ^ ((k >> 31) & 0x7fffffff));
}

// Extract lowest set bit position from 128-bit mask (A:H), branchless; clears it.
// Bit p: q = p>>5, cl = p&31, tag i = 4*cl + q.
__device__ __forceinline__ int ext128(unsigned long long& A, unsigned long long& H) {
    bool ua = (A != 0ull);
    int  pa = __ffsll((long long)A) - 1;
    int  ph = 63 + __ffsll((long long)H);
    int  p  = ua ? pa : ph;
    unsigned long long A2 = A & (A - 1ull);
    unsigned long long H2 = H & (H - 1ull);
    A = ua ? A2 : A;
    H = ua ? H : H2;
    return p;
}

// Exact composite argmax merge: max value, smallest index on ties.
__device__ __forceinline__ void cmerge(float va, int ia, float vb, int ib,
                                       float& vo, int& io) {
    bool g = (vb > va) || (vb == va && ib < ia);
    vo = g ? vb : va;
    io = g ? ib : ia;
}

__global__ void __launch_bounds__(128, 1)
viterbi_kernel(const float* __restrict__ logits,
               const int*   __restrict__ lens,
               const float* __restrict__ trans,
               float*       __restrict__ out)
{
    extern __shared__ float sm[];
    float*    Tt    = sm;
    float*    rminS = sm + RMIN_OFF;
    float*    rmaxS = sm + RMAX_OFF;
    int*      tagsS = (int*)(sm + TAGS_OFF);
    unsigned* bpS   = (unsigned*)(sm + BP_OFF);
    float4*   ring4 = (float4*)(sm + RING_OFF);       // [2][CHUNK][32] float4
    unsigned* metaW = (unsigned*)(sm + META_OFF);     // [3][CHUNK][8] u32

    const int b    = blockIdx.x;
    const int tid  = threadIdx.x;
    const int lane = tid & 31;
    const int warp = tid >> 5;
    const unsigned F = 0xffffffffu;

    int L = lens[b];
    L = L < 1 ? 1 : (L > T_ ? T_ : L);
    const float*  lg  = logits + (size_t)b * T_ * K_;
    const float4* lg4 = (const float4*)lg;            // index: t*32 + c

    // ---- Prologue: transitions -> smem, row-major ----
    {
        const float4* t4g = (const float4*)trans;
        float4*       d4  = (float4*)Tt;
        for (int i = tid; i < (K_ * K_) / 4; i += 128) d4[i] = t4g[i];
    }
    __syncthreads();

    // ---- Per-row min/max (thread = row; rotated column order -> conflict-free) ----
    {
        const float4* rowp = (const float4*)(Tt + tid * K_);
        float mn = __int_as_float(0x7f800000);
        float mx = __int_as_float(0xff800000);
        #pragma unroll
        for (int c0 = 0; c0 < 32; ++c0) {
            int c = (c0 + tid) & 31;
            float4 v = rowp[c];
            mn = fminf(mn, fminf(fminf(v.x, v.y), fminf(v.z, v.w)));
            mx = fmaxf(mx, fmaxf(fmaxf(v.x, v.y), fmaxf(v.z, v.w)));
        }
        rminS[tid] = mn;
        rmaxS[tid] = mx;
    }
    __syncthreads();

    // ---- Global Delta = (tmax - tmin) + slack ----
    if (warp == 0) {
        float mn = fminf(fminf(rminS[lane], rminS[lane + 32]),
                         fminf(rminS[lane + 64], rminS[lane + 96]));
        float mx = fmaxf(fmaxf(rmaxS[lane], rmaxS[lane + 32]),
                         fmaxf(rmaxS[lane + 64], rmaxS[lane + 96]));
        int gmn = __reduce_min_sync(F, f2key(mn));
        int gmx = __reduce_max_sync(F, f2key(mx));
        if (lane == 0) sm[DELTA_OFF] = (key2f(gmx) - key2f(gmn)) + 0.03f;
    }
    __syncthreads();

    // Producer per-lane constants (tags 4*lane..4*lane+3 of each logit row)
    float4 prmn, prxd;
    if (warp != 0) {
        float dlt = sm[DELTA_OFF];
        prmn = ((const float4*)rminS)[lane];
        float4 rx = ((const float4*)rmaxS)[lane];
        prxd = make_float4(rx.x + dlt, rx.y + dlt, rx.z + dlt, rx.w + dlt);
    }

    // Producer row routine: stage row data (for step r) + candidate mask (step r+1).
    // Data slot from r: ring4[ ((r-1)>>4)&1 ][ (r-1)&15 ].  Meta: metaW[(r>>4)%3][r&15].
    auto prod_row = [&](float4 v, int r) {
        if (r >= 1) {
            ring4[ (((r - 1) >> 4) & 1) * (CHUNK * 32) + ((r - 1) & 15) * 32 + lane ] = v;
        }
        float c0 = v.x + prmn.x, c1 = v.y + prmn.y;
        float c2 = v.z + prmn.z, c3 = v.w + prmn.w;
        float cn = fmaxf(fmaxf(c0, c1), fmaxf(c2, c3));
        int   g  = __reduce_max_sync(F, f2key(cn));
        float Gn = key2f(g);
        unsigned nib = (v.x + prxd.x >= Gn ? 1u : 0u) | (v.y + prxd.y >= Gn ? 2u : 0u)
                     | (v.z + prxd.z >= Gn ? 4u : 0u) | (v.w + prxd.w >= Gn ? 8u : 0u);
        unsigned m0 = __ballot_sync(F, (nib & 1u) != 0u);
        unsigned m1 = __ballot_sync(F, (nib & 2u) != 0u);
        unsigned m2 = __ballot_sync(F, (nib & 4u) != 0u);
        unsigned m3 = __ballot_sync(F, (nib & 8u) != 0u);
        unsigned long long A = (unsigned long long)m0 | ((unsigned long long)m1 << 32);
        unsigned long long H = (unsigned long long)m2 | ((unsigned long long)m3 << 32);
        int p0 = ext128(A, H);
        bool more1 = (A | H) != 0ull;
        int p1t = ext128(A, H);
        int p1 = more1 ? p1t : p0;
        bool ovf = (A | H) != 0ull;
        int i0 = 4 * (p0 & 31) + (p0 >> 5);
        int i1 = 4 * (p1 & 31) + (p1 >> 5);
        if (lane == 0) {
            unsigned* mp = metaW + ((r >> 4) % 3) * (CHUNK * 8) + (r & 15) * 8;
            ((uint4*)mp)[0] = make_uint4((unsigned)A, (unsigned)(A >> 32),
                                         (unsigned)H, (unsigned)(H >> 32));
            mp[4] = (unsigned)i0 | ((unsigned)i1 << 8) | (ovf ? 0x10000u : 0u);
        }
    };

    // ---- Prefill: rows 0..16 (masks for steps 1..17, data for steps 1..16) ----
    if (warp != 0) {
        int wi = warp - 1;
        float4 vbuf[6]; int rbuf[6]; int cnt = 0;
        #pragma unroll
        for (int k = 0; k < 6; ++k) {
            int r = 3 * k + wi;
            if (r <= 16) {
                int rc = r < T_ ? r : T_ - 1;
                vbuf[cnt] = lg4[rc * 32 + lane];
                rbuf[cnt] = r;
                ++cnt;
            }
        }
        for (int k = 0; k < cnt; ++k) prod_row(vbuf[k], rbuf[k]);
    }

    float s[4];
    if (warp == 0) {
        float4 v0 = lg4[lane];                        // t=0 logits = init state
        s[0] = v0.x; s[1] = v0.y; s[2] = v0.z; s[3] = v0.w;
    }
    __syncthreads();

    const float4* Trow4 = (const float4*)Tt;          // index: i*32 + lane

    // ---- Chunked forward loop ----
    const int nchunks = (L + CHUNK - 2) / CHUNK;      // ceil((L-1)/CHUNK)
    for (int ci = 0; ci < nchunks; ++ci) {
        const int base = 1 + ci * CHUNK;

        if (warp != 0) {
            // stage rows [base+CHUNK, base+2*CHUNK): data + masks
            int nb = base + CHUNK;
            int wi = warp - 1;
            float4 vbuf[6]; int rbuf[6]; int cnt = 0;
            #pragma unroll
            for (int k = 0; k < 6; ++k) {
                int off = 3 * k + wi;
                if (off < CHUNK) {
                    int r = nb + off;
                    int rc = r < T_ ? r : T_ - 1;
                    vbuf[cnt] = lg4[rc * 32 + lane];
                    rbuf[cnt] = r;
                    ++cnt;
                }
            }
            for (int k = 0; k < cnt; ++k) prod_row(vbuf[k], rbuf[k]);
        } else {
            const float4*   src   = ring4 + (ci & 1) * (CHUNK * 32);
            const unsigned* mslot = metaW + (ci % 3) * (CHUNK * 8);
            int tend = base + CHUNK < L ? base + CHUNK : L;
            for (int t = base; t < tend; ++t) {
                int pos = (t - 1) & 15;
                unsigned w = mslot[pos * 8 + 4];            // meta word (off-chain)
                float4 clt = src[(t - base) * 32 + lane];   // logit row t (off-chain)

                int i0 = (int)(w & 255u);
                int i1 = (int)((w >> 8) & 255u);
                int cl0 = i0 >> 2, q0 = i0 & 3;
                int cl1 = i1 >> 2, q1 = i1 & 3;

                float4 tr0 = Trow4[i0 * 32 + lane];         // addresses state-free
                float4 tr1 = Trow4[i1 * 32 + lane];         // -> off-chain LDS

                // ---- serial chain: sel -> shfl -> add -> merge -> add ----
                float w0 = q0 == 0 ? s[0] : q0 == 1 ? s[1] : q0 == 2 ? s[2] : s[3];
                float w1 = q1 == 0 ? s[0] : q1 == 1 ? s[1] : q1 == 2 ? s[2] : s[3];
                float sc0 = __shfl_sync(F, w0, cl0);
                float sc1 = __shfl_sync(F, w1, cl1);

                float bv0, bv1, bv2, bv3;  int bi0, bi1, bi2, bi3;
                cmerge(sc0 + tr0.x, i0, sc1 + tr1.x, i1, bv0, bi0);
                cmerge(sc0 + tr0.y, i0, sc1 + tr1.y, i1, bv1, bi1);
                cmerge(sc0 + tr0.z, i0, sc1 + tr1.z, i1, bv2, bi2);
                cmerge(sc0 + tr0.w, i0, sc1 + tr1.w, i1, bv3, bi3);

                // ---- rare overflow: remaining candidates from stored mask ----
                if (w & 0x10000u) {
                    const uint4 mr = *(const uint4*)(mslot + pos * 8);
                    unsigned long long A = (unsigned long long)mr.x
                                         | ((unsigned long long)mr.y << 32);
                    unsigned long long H = (unsigned long long)mr.z
                                         | ((unsigned long long)mr.w << 32);
                    while (A | H) {
                        int p = ext128(A, H);
                        int clr = p & 31, qr = p >> 5, ir = 4 * clr + qr;
                        float vr = qr == 0 ? s[0] : qr == 1 ? s[1] : qr == 2 ? s[2] : s[3];
                        float scr = __shfl_sync(F, vr, clr);
                        float4 trr = Trow4[ir * 32 + lane];
                        cmerge(bv0, bi0, scr + trr.x, ir, bv0, bi0);
                        cmerge(bv1, bi1, scr + trr.y, ir, bv1, bi1);
                        cmerge(bv2, bi2, scr + trr.z, ir, bv2, bi2);
                        cmerge(bv3, bi3, scr + trr.w, ir, bv3, bi3);
                    }
                }

                s[0] = bv0 + clt.x;
                s[1] = bv1 + clt.y;
                s[2] = bv2 + clt.z;
                s[3] = bv3 + clt.w;

                bpS[t * 32 + lane] = (unsigned)bi0 | ((unsigned)bi1 << 8) |
                                     ((unsigned)bi2 << 16) | ((unsigned)bi3 << 24);
            }
        }
        __syncthreads();   // chunk handoff (data slot + meta slots rotate)
    }

    if (warp == 0) {
        // ---- last_tag = first argmax of final state ----
        float fm = fmaxf(fmaxf(s[0], s[1]), fmaxf(s[2], s[3]));
        int   mk = __reduce_max_sync(F, f2key(fm));
        unsigned cand = 0x7fffffffu;
        #pragma unroll
        for (int q = 0; q < 4; ++q) {
            unsigned tg = (unsigned)(4 * lane + q);
            cand = (f2key(s[q]) == mk && tg < cand) ? tg : cand;
        }
        int last = (int)__reduce_min_sync(F, cand);

        for (int t = L - 1 + lane; t < T_; t += 32) tagsS[t] = last;

        // ---- backtrack: byte-addressed LDS chain ----
        if (lane == 0) {
            const unsigned char* bpB = (const unsigned char*)bpS;
            int cur = last;
            for (int t = L - 1; t >= 1; --t) {
                cur = bpB[t * 128 + cur];
                tagsS[t - 1] = cur;
            }
        }
    }
    __syncthreads();

    // ---- one-hot epilogue: 512 KB per CTA, coalesced STG.128 ----
    float4* out4 = (float4*)(out + (size_t)b * T_ * K_);
    for (int idx = tid; idx < T_ * (K_ / 4); idx += 128) {
        int t = idx >> 5;
        int c = (idx & 31) * 4;
        int tag = tagsS[t];
        float4 v;
        v.x = (tag == c    ) ? 1.f : 0.f;
        v.y = (tag == c + 1) ? 1.f : 0.f;
        v.z = (tag == c + 2) ? 1.f : 0.f;
        v.w = (tag == c + 3) ? 1.f : 0.f;
        out4[idx] = v;
    }
}

extern "C" void kernel_launch(void* const* d_in, const int* in_sizes, int n_in,
                              void* d_out, int out_size)
{
    const float* logits = (const float*)d_in[0];
    const int*   lens   = (const int*)d_in[1];
    const float* trans  = (const float*)d_in[2];
    float*       out    = (float*)d_out;

    cudaFuncSetAttribute(viterbi_kernel,
                         cudaFuncAttributeMaxDynamicSharedMemorySize,
                         (int)SMEM_BYTES);
    viterbi_kernel<<<B_, 128, SMEM_BYTES>>>(logits, lens, trans, out);
}

// round 15
// speedup vs baseline: 1.5578x; 1.5578x over previous
#include <cuda_runtime.h>
#include <cstdint>

// CRF Viterbi decode: B=128, T=1024, K=128
// out[b,t,k] = one_hot(tags[b,t]) fp32
//
// 1 CTA/batch. Warp 0: serial Viterbi with exact candidate pruning (3-wide
// branchless merge; fmaxf value chain, indices off-chain). Warps 1-3: stage
// logits through a double-buffered smem ring AND compose per-chunk 16-step
// backpointer jump maps in the consumer's shadow. Backtrack = short serial
// tail + 63 map hops + parallel per-chunk replay.

static constexpr int B_ = 128;
static constexpr int T_ = 1024;
static constexpr int K_ = 128;
static constexpr int CHUNK = 16;

static constexpr float BIGF  = 16384.0f;              // positivity bias
static constexpr float SLACK = 0.04f;                 // >= 3x assoc-rounding budget

// Shared memory layout (in 4-byte words)
static constexpr int TT_WORDS  = K_ * K_;             // 16384
static constexpr int RMIN_OFF  = TT_WORDS;            // 16384
static constexpr int RMAX_OFF  = RMIN_OFF + K_;       // 16512
static constexpr int TAGS_OFF  = RMAX_OFF + K_;       // 16640
static constexpr int BP_OFF    = TAGS_OFF + T_;       // 17664
static constexpr int RING_OFF  = BP_OFF + T_ * 32;    // 50432
static constexpr int MAPC_OFF  = RING_OFF + 2 * CHUNK * K_;   // 54528 (64x128 u8)
static constexpr int SMEM_WORDS = MAPC_OFF + (T_ / CHUNK) * K_ / 4;  // 56576
static constexpr size_t SMEM_BYTES = (size_t)SMEM_WORDS * 4;  // 226304 B

__device__ __forceinline__ int f2key(float x) {
    int i = __float_as_int(x);
    return i ^ ((i >> 31) & 0x7fffffff);
}

// Exact composite argmax merge (overflow path only)
__device__ __forceinline__ void cmerge(float va, int ia, float vb, int ib,
                                       float& vo, int& io) {
    bool g = (vb > va) || (vb == va && ib < ia);
    vo = g ? vb : va;
    io = g ? ib : ia;
}

__global__ void __launch_bounds__(128, 1)
viterbi_kernel(const float* __restrict__ logits,
               const int*   __restrict__ lens,
               const float* __restrict__ trans,
               float*       __restrict__ out)
{
    extern __shared__ float sm[];
    float*         Tt    = sm;
    float*         rminS = sm + RMIN_OFF;
    float*         rmaxS = sm + RMAX_OFF;
    int*           tagsS = (int*)(sm + TAGS_OFF);
    unsigned*      bpS   = (unsigned*)(sm + BP_OFF);
    float4*        ring4 = (float4*)(sm + RING_OFF);
    unsigned char* mapc  = (unsigned char*)(sm + MAPC_OFF);
    const unsigned char* bpB = (const unsigned char*)bpS;

    const int b    = blockIdx.x;
    const int tid  = threadIdx.x;
    const int lane = tid & 31;
    const int warp = tid >> 5;
    const unsigned F = 0xffffffffu;

    int L = lens[b];
    L = L < 1 ? 1 : (L > T_ ? T_ : L);
    const float*  lg  = logits + (size_t)b * T_ * K_;
    const float4* lg4 = (const float4*)lg;

    // ---- transitions -> smem ----
    {
        const float4* t4g = (const float4*)trans;
        float4*       d4  = (float4*)Tt;
        for (int i = tid; i < (K_ * K_) / 4; i += 128) d4[i] = t4g[i];
    }
    __syncthreads();

    // ---- per-row min/max ----
    {
        const float4* rowp = (const float4*)(Tt + tid * K_);
        float mn = __int_as_float(0x7f800000);
        float mx = __int_as_float(0xff800000);
        #pragma unroll
        for (int c0 = 0; c0 < 32; ++c0) {
            int c = (c0 + tid) & 31;
            float4 v = rowp[c];
            mn = fminf(mn, fminf(fminf(v.x, v.y), fminf(v.z, v.w)));
            mx = fmaxf(mx, fmaxf(fmaxf(v.x, v.y), fmaxf(v.z, v.w)));
        }
        rminS[tid] = mn;
        rmaxS[tid] = mx;
    }

    // ---- prefill data ring: rows [1, 1+CHUNK) ----
    if (warp != 0) {
        int ptid = tid - 32;
        for (int i = ptid; i < CHUNK * 32; i += 96) {
            int r = 1 + (i >> 5); r = r < T_ ? r : T_ - 1;
            ring4[i] = lg4[r * 32 + (i & 31)];
        }
    }
    __syncthreads();

    // Warp-0 carried registers:
    // bv: pre-logit best; s = bv + clt (off-chain); cnr = clt + rmnb; cxr = clt + rmxb
    float s[4], bv[4], cnr[4], cxr[4], rmnb[4], rmxb[4];
    if (warp == 0) {
        float4 rmn4 = ((const float4*)rminS)[lane];
        float4 rmx4 = ((const float4*)rmaxS)[lane];
        rmnb[0] = rmn4.x + BIGF; rmnb[1] = rmn4.y + BIGF;
        rmnb[2] = rmn4.z + BIGF; rmnb[3] = rmn4.w + BIGF;
        rmxb[0] = (rmx4.x + SLACK) + BIGF; rmxb[1] = (rmx4.y + SLACK) + BIGF;
        rmxb[2] = (rmx4.z + SLACK) + BIGF; rmxb[3] = (rmx4.w + SLACK) + BIGF;
        float4 v0 = lg4[lane];                        // row 0 = init state
        s[0]=v0.x; s[1]=v0.y; s[2]=v0.z; s[3]=v0.w;
        bv[0]=0.f; bv[1]=0.f; bv[2]=0.f; bv[3]=0.f;   // s = bv + row0
        cnr[0]=v0.x+rmnb[0]; cnr[1]=v0.y+rmnb[1];
        cnr[2]=v0.z+rmnb[2]; cnr[3]=v0.w+rmnb[3];
        cxr[0]=v0.x+rmxb[0]; cxr[1]=v0.y+rmxb[1];
        cxr[2]=v0.z+rmxb[2]; cxr[3]=v0.w+rmxb[3];
    }

    const float4* Trow4 = (const float4*)Tt;

    const int nchunks = (L + CHUNK - 2) / CHUNK;      // ceil((L-1)/16); 0 if L==1
    for (int ci = 0; ci < nchunks; ++ci) {
        const int base = 1 + ci * CHUNK;

        if (warp != 0) {
            int ptid = tid - 32;
            // stage next chunk's logit rows
            float4* dst = ring4 + ((ci + 1) & 1) * (CHUNK * 32);
            int nb = base + CHUNK;
            #pragma unroll 2
            for (int i = ptid; i < CHUNK * 32; i += 96) {
                int r = nb + (i >> 5); r = r < T_ ? r : T_ - 1;
                dst[i] = lg4[r * 32 + (i & 31)];
            }
            // compose 16-step backpointer jump map for chunk ci-1 (bp complete)
            int cm = ci - 1;
            if (cm >= 0) {
                for (int x = ptid; x < K_; x += 96) {
                    int cur = x;
                    #pragma unroll
                    for (int k = CHUNK; k >= 1; --k)
                        cur = bpB[(16 * cm + k) * 128 + cur];
                    mapc[cm * 128 + x] = (unsigned char)cur;
                }
            }
        } else {
            const float4* src = ring4 + (ci & 1) * (CHUNK * 32);
            int tend = base + CHUNK < L ? base + CHUNK : L;
            for (int t = base; t < tend; ++t) {
                float4 clt = src[(t - base) * 32 + lane];   // row t (off-chain)

                // ---- chain: anb = bv + cnr -> fmax tree -> raw-bit REDUX ----
                float anb0 = bv[0] + cnr[0], anb1 = bv[1] + cnr[1];
                float anb2 = bv[2] + cnr[2], anb3 = bv[3] + cnr[3];
                float am = fmaxf(fmaxf(anb0, anb1), fmaxf(anb2, anb3));
                int   rI = __reduce_max_sync(F, __float_as_int(am));
                float LBf = __int_as_float(rI);

                float axb0 = bv[0] + cxr[0], axb1 = bv[1] + cxr[1];
                float axb2 = bv[2] + cxr[2], axb3 = bv[3] + cxr[3];
                unsigned nib = (axb0 >= LBf ? 1u : 0u) | (axb1 >= LBf ? 2u : 0u)
                             | (axb2 >= LBf ? 4u : 0u) | (axb3 >= LBf ? 8u : 0u);
                unsigned qf  = nib ? (unsigned)(__ffs(nib) - 1) : 0u;

                unsigned em = __ballot_sync(F, nib != 0u);
                unsigned lo = __ballot_sync(F, (qf & 1u) != 0u);
                unsigned hi = __ballot_sync(F, (qf & 2u) != 0u);
                unsigned mm = __ballot_sync(F, (nib & (nib - 1u)) != 0u);

                // ---- pure-ALU decode of first three candidate lanes ----
                int cl0 = __ffs(em) - 1;
                unsigned em1 = em & (em - 1u);
                unsigned em2 = em1 & (em1 - 1u);
                unsigned em3 = em2 & (em2 - 1u);
                int cl1 = em1 ? (__ffs(em1) - 1) : cl0;
                int cl2 = em2 ? (__ffs(em2) - 1) : cl0;
                int q0 = (int)(((lo >> cl0) & 1u) | (((hi >> cl0) & 1u) << 1));
                int q1 = (int)(((lo >> cl1) & 1u) | (((hi >> cl1) & 1u) << 1));
                int q2 = (int)(((lo >> cl2) & 1u) | (((hi >> cl2) & 1u) << 1));
                int i0 = (cl0 << 2) | q0;
                int i1 = (cl1 << 2) | q1;
                int i2 = (cl2 << 2) | q2;

                float w0 = q0 == 0 ? s[0] : q0 == 1 ? s[1] : q0 == 2 ? s[2] : s[3];
                float w1 = q1 == 0 ? s[0] : q1 == 1 ? s[1] : q1 == 2 ? s[2] : s[3];
                float w2 = q2 == 0 ? s[0] : q2 == 1 ? s[1] : q2 == 2 ? s[2] : s[3];
                float sc0 = __shfl_sync(F, w0, cl0);
                float sc1 = __shfl_sync(F, w1, cl1);
                float sc2 = __shfl_sync(F, w2, cl2);

                float4 tr0 = Trow4[i0 * 32 + lane];   // three LDS.128 in flight
                float4 tr1 = Trow4[i1 * 32 + lane];
                float4 tr2 = Trow4[i2 * 32 + lane];

                // value chain: pure fmaxf; indices resolved off-chain below
                float a00 = sc0 + tr0.x, a01 = sc1 + tr1.x, a02 = sc2 + tr2.x;
                float a10 = sc0 + tr0.y, a11 = sc1 + tr1.y, a12 = sc2 + tr2.y;
                float a20 = sc0 + tr0.z, a21 = sc1 + tr1.z, a22 = sc2 + tr2.z;
                float a30 = sc0 + tr0.w, a31 = sc1 + tr1.w, a32 = sc2 + tr2.w;
                float bv0 = fmaxf(fmaxf(a00, a01), a02);
                float bv1 = fmaxf(fmaxf(a10, a11), a12);
                float bv2 = fmaxf(fmaxf(a20, a21), a22);
                float bv3 = fmaxf(fmaxf(a30, a31), a32);

                // indices (i0 < i1 < i2 when distinct; ties -> smallest index)
                int bi0 = (a01 > a00) ? ((a02 > a01) ? i2 : i1) : ((a02 > a00) ? i2 : i0);
                int bi1 = (a11 > a10) ? ((a12 > a11) ? i2 : i1) : ((a12 > a10) ? i2 : i0);
                int bi2 = (a21 > a20) ? ((a22 > a21) ? i2 : i1) : ((a22 > a20) ? i2 : i0);
                int bi3 = (a31 > a30) ? ((a32 > a31) ? i2 : i1) : ((a32 > a30) ? i2 : i0);

                // ---- rare overflow: >=4 candidate lanes or multi-slot lanes ----
                unsigned rem = (em3 ? em3 : 0u) | mm;
                if (rem) {
                    do {
                        int cl = __ffs(rem) - 1; rem &= rem - 1u;
                        unsigned nb = __shfl_sync(F, nib, cl);
                        while (nb) {
                            int q = __ffs(nb) - 1; nb &= nb - 1u;
                            int i = (cl << 2) | q;
                            float sv = q == 0 ? s[0] : q == 1 ? s[1] : q == 2 ? s[2] : s[3];
                            float sc = __shfl_sync(F, sv, cl);
                            float4 tr = Trow4[i * 32 + lane];
                            cmerge(bv0, bi0, sc + tr.x, i, bv0, bi0);
                            cmerge(bv1, bi1, sc + tr.y, i, bv1, bi1);
                            cmerge(bv2, bi2, sc + tr.z, i, bv2, bi2);
                            cmerge(bv3, bi3, sc + tr.w, i, bv3, bi3);
                        }
                    } while (rem);
                }

                // ---- carried values (s, cnr, cxr off the critical chain) ----
                bv[0] = bv0; bv[1] = bv1; bv[2] = bv2; bv[3] = bv3;
                s[0] = bv0 + clt.x;
                s[1] = bv1 + clt.y;
                s[2] = bv2 + clt.z;
                s[3] = bv3 + clt.w;
                cnr[0] = clt.x + rmnb[0]; cxr[0] = clt.x + rmxb[0];
                cnr[1] = clt.y + rmnb[1]; cxr[1] = clt.y + rmxb[1];
                cnr[2] = clt.z + rmnb[2]; cxr[2] = clt.z + rmxb[2];
                cnr[3] = clt.w + rmnb[3]; cxr[3] = clt.w + rmxb[3];

                bpS[t * 32 + lane] = (unsigned)bi0 | ((unsigned)bi1 << 8) |
                                     ((unsigned)bi2 << 16) | ((unsigned)bi3 << 24);
            }
        }
        __syncthreads();
    }

    if (warp == 0) {
        // ---- last_tag = first argmax of final state ----
        float fm = fmaxf(fmaxf(s[0], s[1]), fmaxf(s[2], s[3]));
        int   mk = __reduce_max_sync(F, f2key(fm));
        unsigned cand = 0x7fffffffu;
        #pragma unroll
        for (int q = 0; q < 4; ++q) {
            unsigned tg = (unsigned)(4 * lane + q);
            cand = (f2key(s[q]) == mk && tg < cand) ? tg : cand;
        }
        int last = (int)__reduce_min_sync(F, cand);

        for (int t = L - 1 + lane; t < T_; t += 32) tagsS[t] = last;

        if (lane == 0) {
            // serial tail down to the top full-chunk boundary
            int tlow = nchunks >= 1 ? (16 * (nchunks - 1) + 1) : 1;
            int cur = last;
            for (int t = L - 1; t >= tlow; --t) {
                cur = bpB[t * 128 + cur];
                tagsS[t - 1] = cur;
            }
            // hop composed chunk maps down to t = 0 boundary
            if (nchunks >= 2) {
                for (int c = nchunks - 2; c >= 0; --c)
                    tagsS[16 * c] = (int)mapc[c * 128 + tagsS[16 * (c + 1)]];
            }
        }
    }
    __syncthreads();

    // ---- parallel per-chunk replay of interior tags ----
    if (tid < nchunks - 1) {
        int c = tid;
        int x = tagsS[16 * (c + 1)];
        #pragma unroll
        for (int k = CHUNK; k >= 1; --k) {
            x = bpB[(16 * c + k) * 128 + x];
            tagsS[16 * c + k - 1] = x;
        }
    }
    __syncthreads();

    // ---- one-hot epilogue ----
    float4* out4 = (float4*)(out + (size_t)b * T_ * K_);
    for (int idx = tid; idx < T_ * (K_ / 4); idx += 128) {
        int t = idx >> 5;
        int c = (idx & 31) * 4;
        int tag = tagsS[t];
        float4 v;
        v.x = (tag == c    ) ? 1.f : 0.f;
        v.y = (tag == c + 1) ? 1.f : 0.f;
        v.z = (tag == c + 2) ? 1.f : 0.f;
        v.w = (tag == c + 3) ? 1.f : 0.f;
        out4[idx] = v;
    }
}

extern "C" void kernel_launch(void* const* d_in, const int* in_sizes, int n_in,
                              void* d_out, int out_size)
{
    const float* logits = (const float*)d_in[0];
    const int*   lens   = (const int*)d_in[1];
    const float* trans  = (const float*)d_in[2];
    float*       out    = (float*)d_out;

    cudaFuncSetAttribute(viterbi_kernel,
                         cudaFuncAttributeMaxDynamicSharedMemorySize,
                         (int)SMEM_BYTES);
    viterbi_kernel<<<B_, 128, SMEM_BYTES>>>(logits, lens, trans, out);
}